// round 6
// baseline (speedup 1.0000x reference)
#include <cuda_runtime.h>

#define NN 1024
#define DD 256
#define DK 32        // d-chunk in shared
#define GRP 16       // lg2 flush group

// scratch: normalized mu and sigma^2 = exp(log_sigma)
__device__ float g_mu[NN * DD];
__device__ float g_s[NN * DD];

__device__ __forceinline__ float frcp(float x) {
    float r; asm("rcp.approx.ftz.f32 %0, %1;" : "=f"(r) : "f"(x)); return r;
}
__device__ __forceinline__ float flg2(float x) {
    float r; asm("lg2.approx.ftz.f32 %0, %1;" : "=f"(r) : "f"(x)); return r;
}

// One block per row: normalize mu_X row (F.normalize, eps=1e-12) and exp(log_sigma).
__global__ void prep_kernel(const float* __restrict__ muX,
                            const float* __restrict__ logsig) {
    const int row = blockIdx.x;
    const int t = threadIdx.x;  // 256 threads == DD
    float x = muX[row * DD + t];
    float v = x * x;
    #pragma unroll
    for (int o = 16; o; o >>= 1) v += __shfl_xor_sync(0xffffffffu, v, o);
    __shared__ float red[8];
    __shared__ float inv_sh;
    if ((t & 31) == 0) red[t >> 5] = v;
    __syncthreads();
    if (t == 0) {
        float tot = 0.f;
        #pragma unroll
        for (int k = 0; k < 8; k++) tot += red[k];
        inv_sh = 1.0f / fmaxf(sqrtf(tot), 1e-12f);
    }
    __syncthreads();
    g_mu[row * DD + t] = x * inv_sh;
    g_s[row * DD + t] = expf(logsig[row * DD + t]);
}

// 64x64 output tile per block, 256 threads, 16 outputs/thread (4i x 4j).
// Only upper-triangular tiles (tj >= ti) work; results mirrored.
// ln-terms accumulated as log2 of a running product (one lg2 per 16 d's).
__global__ __launch_bounds__(256) void pair_kernel(float* __restrict__ out) {
    const int ti = blockIdx.y, tj = blockIdx.x;
    if (tj < ti) return;

    // [d][row] layout, pad 65: load (lane=d, stride 65 -> bank l+r) and
    // compute (row-consecutive) both conflict-free.
    __shared__ float smui[DK][65];
    __shared__ float ssi [DK][65];
    __shared__ float smuj[DK][65];
    __shared__ float ssj [DK][65];

    const int t   = threadIdx.x;
    const int txj = t & 15;   // j base within tile (j = txj + 16q)
    const int ty  = t >> 4;   // i base within tile (i = ty + 16k)
    const int i0 = ti * 64, j0 = tj * 64;

    float acc[4][4];
    float prod[4][4];
    #pragma unroll
    for (int k = 0; k < 4; k++)
        #pragma unroll
        for (int q = 0; q < 4; q++) { acc[k][q] = 0.f; prod[k][q] = 1.f; }

    for (int dc = 0; dc < DD; dc += DK) {
        __syncthreads();
        // cooperative load: per iter p, warp handles one row r, lane = d
        #pragma unroll
        for (int p = 0; p < 8; p++) {
            int idx = t + 256 * p;        // 0..2047
            int d = idx & 31;
            int r = idx >> 5;             // 0..63
            smui[d][r] = g_mu[(i0 + r) * DD + dc + d];
            ssi [d][r] = g_s [(i0 + r) * DD + dc + d];
            smuj[d][r] = g_mu[(j0 + r) * DD + dc + d];
            ssj [d][r] = g_s [(j0 + r) * DD + dc + d];
        }
        __syncthreads();

        #pragma unroll
        for (int g = 0; g < DK / GRP; g++) {
            #pragma unroll 4
            for (int dd = 0; dd < GRP; dd++) {
                const int d = g * GRP + dd;
                float mj[4], sj[4], mi[4], si[4];
                #pragma unroll
                for (int q = 0; q < 4; q++) {
                    mj[q] = smuj[d][txj + 16 * q];
                    sj[q] = ssj [d][txj + 16 * q];
                }
                #pragma unroll
                for (int k = 0; k < 4; k++) {
                    mi[k] = smui[d][ty + 16 * k];   // broadcast
                    si[k] = ssi [d][ty + 16 * k];
                }
                #pragma unroll
                for (int k = 0; k < 4; k++)
                    #pragma unroll
                    for (int q = 0; q < 4; q++) {
                        float ssum = si[k] + sj[q];
                        float diff = mi[k] - mj[q];
                        acc[k][q]  = fmaf(diff * diff, frcp(ssum), acc[k][q]);
                        prod[k][q] = prod[k][q] * ssum;
                    }
            }
            // flush: acc += ln(prod) = lg2(prod) * ln2
            #pragma unroll
            for (int k = 0; k < 4; k++)
                #pragma unroll
                for (int q = 0; q < 4; q++) {
                    acc[k][q] = fmaf(flg2(prod[k][q]), 0.6931471805599453f, acc[k][q]);
                    prod[k][q] = 1.0f;
                }
        }
    }

    const bool diag = (ti == tj);
    #pragma unroll
    for (int k = 0; k < 4; k++) {
        int i = i0 + ty + 16 * k;
        #pragma unroll
        for (int q = 0; q < 4; q++) {
            int j = j0 + txj + 16 * q;
            float v = -acc[k][q];
            out[i * NN + j] = v;               // coalesced
            if (!diag) out[j * NN + i] = v;    // mirrored
        }
    }
}

extern "C" void kernel_launch(void* const* d_in, const int* in_sizes, int n_in,
                              void* d_out, int out_size) {
    const float* muX  = (const float*)d_in[0];
    const float* lsig = (const float*)d_in[1];
    float* out = (float*)d_out;

    prep_kernel<<<NN, DD>>>(muX, lsig);

    dim3 grid(NN / 64, NN / 64);   // lower-triangle blocks exit immediately
    pair_kernel<<<grid, 256>>>(out);
}

// round 8
// speedup vs baseline: 1.0922x; 1.0922x over previous
#include <cuda_runtime.h>

#define NN 1024
#define DD 256
#define DK 32        // d-chunk in shared
#define GRP 16       // lg2 flush group

// scratch: normalized mu and sigma^2 = exp(log_sigma)
__device__ float g_mu[NN * DD];
__device__ float g_s[NN * DD];

typedef unsigned long long u64;

__device__ __forceinline__ float frcp(float x) {
    float r; asm("rcp.approx.ftz.f32 %0, %1;" : "=f"(r) : "f"(x)); return r;
}
__device__ __forceinline__ float flg2(float x) {
    float r; asm("lg2.approx.ftz.f32 %0, %1;" : "=f"(r) : "f"(x)); return r;
}
__device__ __forceinline__ u64 pk(float lo, float hi) {
    u64 r; asm("mov.b64 %0, {%1, %2};" : "=l"(r) : "f"(lo), "f"(hi)); return r;
}
__device__ __forceinline__ void upk(u64 v, float& lo, float& hi) {
    asm("mov.b64 {%0, %1}, %2;" : "=f"(lo), "=f"(hi) : "l"(v));
}
__device__ __forceinline__ u64 add2(u64 a, u64 b) {
    u64 r; asm("add.rn.f32x2 %0, %1, %2;" : "=l"(r) : "l"(a), "l"(b)); return r;
}
__device__ __forceinline__ u64 mul2(u64 a, u64 b) {
    u64 r; asm("mul.rn.f32x2 %0, %1, %2;" : "=l"(r) : "l"(a), "l"(b)); return r;
}
__device__ __forceinline__ u64 fma2(u64 a, u64 b, u64 c) {
    u64 r; asm("fma.rn.f32x2 %0, %1, %2, %3;" : "=l"(r) : "l"(a), "l"(b), "l"(c)); return r;
}

// One block per row: normalize mu_X row (F.normalize, eps=1e-12) and exp(log_sigma).
__global__ void prep_kernel(const float* __restrict__ muX,
                            const float* __restrict__ logsig) {
    const int row = blockIdx.x;
    const int t = threadIdx.x;  // 256 threads == DD
    float x = muX[row * DD + t];
    float v = x * x;
    #pragma unroll
    for (int o = 16; o; o >>= 1) v += __shfl_xor_sync(0xffffffffu, v, o);
    __shared__ float red[8];
    __shared__ float inv_sh;
    if ((t & 31) == 0) red[t >> 5] = v;
    __syncthreads();
    if (t == 0) {
        float tot = 0.f;
        #pragma unroll
        for (int k = 0; k < 8; k++) tot += red[k];
        inv_sh = 1.0f / fmaxf(sqrtf(tot), 1e-12f);
    }
    __syncthreads();
    g_mu[row * DD + t] = x * inv_sh;
    g_s[row * DD + t] = expf(logsig[row * DD + t]);
}

// 64x64 output tile per block, 512 threads, 8 outputs/thread (2i x 4j).
// j's = {2txj, 2txj+1, 2txj+32, 2txj+33} (two packed f32x2 pairs),
// i's = {2ty, 2ty+1}. All pairwise math in packed f32x2; rcp/lg2 scalar MUFU.
// j-tile mu stored NEGATED so diff = packed add. ln-terms via one lg2 per
// 16 d's (log of running product).
__global__ __launch_bounds__(512) void pair_kernel(float* __restrict__ out) {
    const int ti = blockIdx.y, tj = blockIdx.x;
    if (tj < ti) return;

    // [d][row] layout, pad 66 (even -> 8B-aligned float2 at even columns).
    __shared__ float smui [DK][66];
    __shared__ float ssi  [DK][66];
    __shared__ float smujn[DK][66];   // negated mu for j tile
    __shared__ float ssj  [DK][66];

    const int t   = threadIdx.x;
    const int txj = t & 15;   // j pair bases: 2*txj, 2*txj+32
    const int ty  = t >> 4;   // 0..31; i = 2*ty + k
    const int i0 = ti * 64, j0 = tj * 64;

    const u64 ONE2 = pk(1.0f, 1.0f);
    const u64 LN2  = pk(0.6931471805599453f, 0.6931471805599453f);

    u64 acc[2][2], prod[2][2];
    #pragma unroll
    for (int k = 0; k < 2; k++)
        #pragma unroll
        for (int q = 0; q < 2; q++) { acc[k][q] = pk(0.f, 0.f); prod[k][q] = ONE2; }

    for (int dc = 0; dc < DD; dc += DK) {
        __syncthreads();
        #pragma unroll
        for (int p = 0; p < 4; p++) {
            int idx = t + 512 * p;     // 0..2047
            int d = idx & 31;
            int r = idx >> 5;          // 0..63
            smui [d][r] =  g_mu[(i0 + r) * DD + dc + d];
            ssi  [d][r] =  g_s [(i0 + r) * DD + dc + d];
            smujn[d][r] = -g_mu[(j0 + r) * DD + dc + d];
            ssj  [d][r] =  g_s [(j0 + r) * DD + dc + d];
        }
        __syncthreads();

        #pragma unroll
        for (int g = 0; g < DK / GRP; g++) {
            #pragma unroll 4
            for (int dd = 0; dd < GRP; dd++) {
                const int d = g * GRP + dd;
                // vector shared loads (LDS.64), conflict-free / broadcast
                u64 mjn[2], sj[2];
                mjn[0] = *(const u64*)&smujn[d][2 * txj];
                mjn[1] = *(const u64*)&smujn[d][2 * txj + 32];
                sj[0]  = *(const u64*)&ssj  [d][2 * txj];
                sj[1]  = *(const u64*)&ssj  [d][2 * txj + 32];
                float2 miv = *(const float2*)&smui[d][2 * ty];
                float2 siv = *(const float2*)&ssi [d][2 * ty];
                u64 mi[2] = { pk(miv.x, miv.x), pk(miv.y, miv.y) };
                u64 si[2] = { pk(siv.x, siv.x), pk(siv.y, siv.y) };

                #pragma unroll
                for (int k = 0; k < 2; k++)
                    #pragma unroll
                    for (int q = 0; q < 2; q++) {
                        u64 ssum = add2(si[k], sj[q]);
                        u64 diff = add2(mi[k], mjn[q]);
                        u64 sq   = mul2(diff, diff);
                        float lo, hi; upk(ssum, lo, hi);
                        u64 rc = pk(frcp(lo), frcp(hi));
                        acc[k][q]  = fma2(sq, rc, acc[k][q]);
                        prod[k][q] = mul2(prod[k][q], ssum);
                    }
            }
            // flush: acc += ln(prod) = lg2(prod) * ln2
            #pragma unroll
            for (int k = 0; k < 2; k++)
                #pragma unroll
                for (int q = 0; q < 2; q++) {
                    float plo, phi; upk(prod[k][q], plo, phi);
                    u64 lg = pk(flg2(plo), flg2(phi));
                    acc[k][q] = fma2(lg, LN2, acc[k][q]);
                    prod[k][q] = ONE2;
                }
        }
    }

    const bool diag = (ti == tj);
    float a[2][4];
    #pragma unroll
    for (int k = 0; k < 2; k++) {
        upk(acc[k][0], a[k][0], a[k][1]);
        upk(acc[k][1], a[k][2], a[k][3]);
        #pragma unroll
        for (int q = 0; q < 4; q++) a[k][q] = -a[k][q];
    }
    // coalesced stores: row i, column pairs (2txj, 2txj+1) and (+32)
    #pragma unroll
    for (int k = 0; k < 2; k++) {
        int i = i0 + 2 * ty + k;
        *(float2*)&out[i * NN + j0 + 2 * txj]      = make_float2(a[k][0], a[k][1]);
        *(float2*)&out[i * NN + j0 + 2 * txj + 32] = make_float2(a[k][2], a[k][3]);
    }
    // mirrored stores: column j, row pair (2ty, 2ty+1) -> float2 per j
    if (!diag) {
        #pragma unroll
        for (int q = 0; q < 4; q++) {
            int j = j0 + 2 * txj + (q & 1) + (q >> 1) * 32;
            int qi = (q & 1) | ((q >> 1) << 1);  // which acc column: 0,?,... map below
            // acc column index for this j: pair q>>1, lane q&1
            float v0 = a[0][(q >> 1) * 2 + (q & 1)];
            float v1 = a[1][(q >> 1) * 2 + (q & 1)];
            (void)qi;
            *(float2*)&out[j * NN + i0 + 2 * ty] = make_float2(v0, v1);
        }
    }
}

extern "C" void kernel_launch(void* const* d_in, const int* in_sizes, int n_in,
                              void* d_out, int out_size) {
    const float* muX  = (const float*)d_in[0];
    const float* lsig = (const float*)d_in[1];
    float* out = (float*)d_out;

    prep_kernel<<<NN, DD>>>(muX, lsig);

    dim3 grid(NN / 64, NN / 64);   // lower-triangle blocks exit immediately
    pair_kernel<<<grid, 512>>>(out);
}

// round 10
// speedup vs baseline: 2.0281x; 1.8569x over previous
#include <cuda_runtime.h>

#define NN 1024
#define DD 256
#define DK 32       // d-chunk in shared
#define DHALF 128   // d-range per block (d-split by 2)

// scratch: normalized mu and sigma^2 = exp(log_sigma)
__device__ float g_mu[NN * DD];
__device__ float g_s[NN * DD];

__device__ __forceinline__ float frcp(float x) {
    float r; asm("rcp.approx.ftz.f32 %0, %1;" : "=f"(r) : "f"(x)); return r;
}
__device__ __forceinline__ float flg2(float x) {
    float r; asm("lg2.approx.ftz.f32 %0, %1;" : "=f"(r) : "f"(x)); return r;
}
__device__ __forceinline__ void gred(float* p, float v) {
    asm volatile("red.global.add.f32 [%0], %1;" :: "l"(p), "f"(v) : "memory");
}

// One block per row: normalize mu_X row (F.normalize, eps=1e-12) and exp(log_sigma).
__global__ void prep_kernel(const float* __restrict__ muX,
                            const float* __restrict__ logsig) {
    const int row = blockIdx.x;
    const int t = threadIdx.x;  // 256 threads == DD
    float x = muX[row * DD + t];
    float v = x * x;
    #pragma unroll
    for (int o = 16; o; o >>= 1) v += __shfl_xor_sync(0xffffffffu, v, o);
    __shared__ float red[8];
    __shared__ float inv_sh;
    if ((t & 31) == 0) red[t >> 5] = v;
    __syncthreads();
    if (t == 0) {
        float tot = 0.f;
        #pragma unroll
        for (int k = 0; k < 8; k++) tot += red[k];
        inv_sh = 1.0f / fmaxf(sqrtf(tot), 1e-12f);
    }
    __syncthreads();
    g_mu[row * DD + t] = x * inv_sh;
    g_s[row * DD + t] = expf(logsig[row * DD + t]);
}

__global__ void zero_kernel(float* __restrict__ out) {
    int i = blockIdx.x * 256 + threadIdx.x;
    ((float4*)out)[i] = make_float4(0.f, 0.f, 0.f, 0.f);
}

// 64x64 output tile, 512 threads, 8 outputs/thread (2i x 4j), scalar math.
// grid.x = 136 dense upper-triangular tiles; grid.y = 2 d-halves (272 blocks
// total -> 2 blocks/SM, 8 warps/SMSP). Each block RED-adds its partial (over
// 128 d's) into the zeroed output; mirror handled by both halves.
// Inner trick: pair-combine over d: sq1/a + sq2/b = (sq1*b + sq2*a)*rcp(a*b),
// and a*b feeds the running product for the batched ln (one lg2 per 8 d's).
__global__ __launch_bounds__(512, 2) void pair_kernel(float* __restrict__ out) {
    // closed-form dense upper-triangular tile decode (T = 16 tiles/side):
    // b = sum_{r<ti}(16-r) + (tj-ti)
    const int b = blockIdx.x;
    int ti = (int)(16.5f - sqrtf(16.5f * 16.5f - 2.0f * (float)b + 0.25f));
    // guard against fp edge cases
    while (ti > 0 && b < (ti * (33 - ti)) / 2) ti--;
    while (b >= ((ti + 1) * (32 - ti)) / 2) ti++;
    const int tj = ti + (b - (ti * (33 - ti)) / 2);
    const int h = blockIdx.y;

    // interleaved (mu0, mu1, s0, s1) per row-pair; [pair][d] with d padded
    // to 33: STS.128 consecutive-d perfect, LDS.128 j-loads 2-phase optimal,
    // i-loads broadcast. j-side mu stored NEGATED (diff = add).
    __shared__ float4 s_i[32][33];
    __shared__ float4 s_j[32][33];

    const int t   = threadIdx.x;
    const int txj = t & 15;   // j pairs: txj, txj+16  -> j = 2txj,2txj+1,2txj+32,2txj+33
    const int ty  = t >> 4;   // i pair: i = 2ty, 2ty+1
    const int i0 = ti * 64, j0 = tj * 64;
    const int dbase = h * DHALF;

    float acc[2][4], prod[2][4];
    #pragma unroll
    for (int k = 0; k < 2; k++)
        #pragma unroll
        for (int q = 0; q < 4; q++) { acc[k][q] = 0.f; prod[k][q] = 1.f; }

    for (int dc = 0; dc < DHALF; dc += DK) {
        __syncthreads();
        // cooperative load: 2 sides x 32 d x 32 pairs = 2048 float4 / 512 thr
        #pragma unroll
        for (int p = 0; p < 4; p++) {
            int idx = t + 512 * p;
            int d    = idx & 31;          // lane-consecutive -> coalesced LDG
            int pr   = (idx >> 5) & 31;
            int side = idx >> 10;
            int gd = dbase + dc + d;
            if (side == 0) {
                int r = (i0 + 2 * pr) * DD + gd;
                s_i[pr][d] = make_float4(g_mu[r], g_mu[r + DD], g_s[r], g_s[r + DD]);
            } else {
                int r = (j0 + 2 * pr) * DD + gd;
                s_j[pr][d] = make_float4(-g_mu[r], -g_mu[r + DD], g_s[r], g_s[r + DD]);
            }
        }
        __syncthreads();

        #pragma unroll 1
        for (int g = 0; g < DK / 8; g++) {      // 8 d's per group, flush per group
            #pragma unroll
            for (int dp = 0; dp < 4; dp++) {    // d-pairs (da, db)
                const int d = g * 8 + dp * 2;
                float4 ia  = s_i[ty][d],       ib  = s_i[ty][d + 1];
                float4 j0a = s_j[txj][d],      j0b = s_j[txj][d + 1];
                float4 j1a = s_j[txj + 16][d], j1b = s_j[txj + 16][d + 1];

                float mia[2] = { ia.x, ia.y }, sia[2] = { ia.z, ia.w };
                float mib[2] = { ib.x, ib.y }, sib[2] = { ib.z, ib.w };
                float mja[4] = { j0a.x, j0a.y, j1a.x, j1a.y };
                float sja[4] = { j0a.z, j0a.w, j1a.z, j1a.w };
                float mjb[4] = { j0b.x, j0b.y, j1b.x, j1b.y };
                float sjb[4] = { j0b.z, j0b.w, j1b.z, j1b.w };

                #pragma unroll
                for (int k = 0; k < 2; k++)
                    #pragma unroll
                    for (int q = 0; q < 4; q++) {
                        float a  = sia[k] + sja[q];        // ssum at da
                        float bb = sib[k] + sjb[q];        // ssum at db
                        float d1 = mia[k] + mja[q];        // mu_i - mu_j (j negated)
                        float d2 = mib[k] + mjb[q];
                        float s1 = d1 * d1;
                        float s2 = d2 * d2;
                        float den = a * bb;
                        float num = s1 * bb;
                        num = fmaf(s2, a, num);
                        acc[k][q]  = fmaf(num, frcp(den), acc[k][q]);
                        prod[k][q] = prod[k][q] * den;
                    }
            }
            // flush: acc += ln(prod of 8 ssums)
            #pragma unroll
            for (int k = 0; k < 2; k++)
                #pragma unroll
                for (int q = 0; q < 4; q++) {
                    acc[k][q] = fmaf(flg2(prod[k][q]), 0.6931471805599453f, acc[k][q]);
                    prod[k][q] = 1.0f;
                }
        }
    }

    // RED partial (-acc) into zero-initialized out; mirror unless diagonal tile.
    const bool diag = (ti == tj);
    #pragma unroll
    for (int k = 0; k < 2; k++) {
        int i = i0 + 2 * ty + k;
        #pragma unroll
        for (int q = 0; q < 4; q++) {
            int j = j0 + 2 * txj + (q & 1) + (q >> 1) * 32;
            float v = -acc[k][q];
            gred(&out[i * NN + j], v);
            if (!diag) gred(&out[j * NN + i], v);
        }
    }
}

extern "C" void kernel_launch(void* const* d_in, const int* in_sizes, int n_in,
                              void* d_out, int out_size) {
    const float* muX  = (const float*)d_in[0];
    const float* lsig = (const float*)d_in[1];
    float* out = (float*)d_out;

    prep_kernel<<<NN, DD>>>(muX, lsig);
    zero_kernel<<<NN * NN / 4 / 256, 256>>>(out);

    dim3 grid(136, 2);   // dense triangular tiles x d-halves
    pair_kernel<<<grid, 512>>>(out);
}

// round 11
// speedup vs baseline: 2.1307x; 1.0506x over previous
#include <cuda_runtime.h>

#define NN 1024
#define DD 256
#define DK 32       // d-chunk in shared
#define DHALF 128   // d-range per block (d-split by 2)

// scratch: normalized mu and sigma^2 = exp(log_sigma)
__device__ float g_mu[NN * DD];
__device__ float g_s[NN * DD];

typedef unsigned long long u64;

__device__ __forceinline__ float frcp(float x) {
    float r; asm("rcp.approx.ftz.f32 %0, %1;" : "=f"(r) : "f"(x)); return r;
}
__device__ __forceinline__ float flg2(float x) {
    float r; asm("lg2.approx.ftz.f32 %0, %1;" : "=f"(r) : "f"(x)); return r;
}
__device__ __forceinline__ void gred(float* p, float v) {
    asm volatile("red.global.add.f32 [%0], %1;" :: "l"(p), "f"(v) : "memory");
}
__device__ __forceinline__ u64 pk(float lo, float hi) {
    u64 r; asm("mov.b64 %0, {%1, %2};" : "=l"(r) : "f"(lo), "f"(hi)); return r;
}
__device__ __forceinline__ void upk(u64 v, float& lo, float& hi) {
    asm("mov.b64 {%0, %1}, %2;" : "=f"(lo), "=f"(hi) : "l"(v));
}
// the ONLY packed math op we trust to hit FFMA2 hardware
__device__ __forceinline__ u64 fma2(u64 a, u64 b, u64 c) {
    u64 r; asm("fma.rn.f32x2 %0, %1, %2, %3;" : "=l"(r) : "l"(a), "l"(b), "l"(c)); return r;
}

// warp-per-row prep: normalize mu_X row (F.normalize, eps=1e-12) and exp(log_sigma).
// 8 rows per 256-thread block, float4 I/O.
__global__ void prep_kernel(const float* __restrict__ muX,
                            const float* __restrict__ logsig) {
    const int lane = threadIdx.x & 31;
    const int row = blockIdx.x * 8 + (threadIdx.x >> 5);
    const float4* mu4 = (const float4*)(muX   + row * DD);
    const float4* ls4 = (const float4*)(logsig + row * DD);
    float4 a = mu4[lane], b = mu4[lane + 32];
    float v = a.x*a.x + a.y*a.y + a.z*a.z + a.w*a.w
            + b.x*b.x + b.y*b.y + b.z*b.z + b.w*b.w;
    #pragma unroll
    for (int o = 16; o; o >>= 1) v += __shfl_xor_sync(0xffffffffu, v, o);
    float inv = rsqrtf(fmaxf(v, 1e-24f));
    float4* gm4 = (float4*)(g_mu + row * DD);
    float4* gs4 = (float4*)(g_s  + row * DD);
    gm4[lane]      = make_float4(a.x*inv, a.y*inv, a.z*inv, a.w*inv);
    gm4[lane + 32] = make_float4(b.x*inv, b.y*inv, b.z*inv, b.w*inv);
    float4 la = ls4[lane], lb = ls4[lane + 32];
    gs4[lane]      = make_float4(expf(la.x), expf(la.y), expf(la.z), expf(la.w));
    gs4[lane + 32] = make_float4(expf(lb.x), expf(lb.y), expf(lb.z), expf(lb.w));
}

__global__ void zero_kernel(float* __restrict__ out) {
    int i = blockIdx.x * 256 + threadIdx.x;
    ((float4*)out)[i] = make_float4(0.f, 0.f, 0.f, 0.f);
}

// 64x64 output tile, 512 threads, 8 outputs/thread (2i x 4j).
// grid.x = 136 dense upper-triangular tiles; grid.y = 2 d-halves (272 blocks,
// 2 blocks/SM). Partials RED-added into zeroed output (2 deterministic adds).
// Inner math entirely packed fma.rn.f32x2 (FFMA2) across the 2 adjacent j's
// of a pair; d-pair combine halves RCP: sq1/a + sq2/b = (sq1*b+sq2*a)*rcp(ab),
// with a*b feeding the batched-ln running product (one lg2 per 8 d's).
__global__ __launch_bounds__(512, 2) void pair_kernel(float* __restrict__ out) {
    // dense upper-triangular tile decode (16 tiles/side)
    const int b = blockIdx.x;
    int ti = (int)(16.5f - sqrtf(16.5f * 16.5f - 2.0f * (float)b + 0.25f));
    while (ti > 0 && b < (ti * (33 - ti)) / 2) ti--;
    while (b >= ((ti + 1) * (32 - ti)) / 2) ti++;
    const int tj = ti + (b - (ti * (33 - ti)) / 2);
    const int h = blockIdx.y;

    // interleaved (mu0, mu1, s0, s1) per row-pair; [pair][d] pad 33.
    // j-side mu stored NEGATED (diff = add).
    __shared__ float4 s_i[32][33];
    __shared__ float4 s_j[32][33];

    const int t   = threadIdx.x;
    const int txj = t & 15;   // j pairs: txj, txj+16 -> j = 2txj,2txj+1,2txj+32,2txj+33
    const int ty  = t >> 4;   // i pair: i = 2ty, 2ty+1
    const int i0 = ti * 64, j0 = tj * 64;
    const int dbase = h * DHALF;

    const u64 ONE2  = pk(1.0f, 1.0f);
    const u64 ZERO2 = 0ull;                  // {0.0f, 0.0f}
    const u64 LN2_2 = pk(0.6931471805599453f, 0.6931471805599453f);

    u64 acc2[2][2], prod2[2][2];
    #pragma unroll
    for (int k = 0; k < 2; k++)
        #pragma unroll
        for (int jp = 0; jp < 2; jp++) { acc2[k][jp] = ZERO2; prod2[k][jp] = ONE2; }

    for (int dc = 0; dc < DHALF; dc += DK) {
        __syncthreads();
        #pragma unroll
        for (int p = 0; p < 4; p++) {
            int idx = t + 512 * p;
            int d    = idx & 31;
            int pr   = (idx >> 5) & 31;
            int side = idx >> 10;
            int gd = dbase + dc + d;
            if (side == 0) {
                int r = (i0 + 2 * pr) * DD + gd;
                s_i[pr][d] = make_float4(g_mu[r], g_mu[r + DD], g_s[r], g_s[r + DD]);
            } else {
                int r = (j0 + 2 * pr) * DD + gd;
                s_j[pr][d] = make_float4(-g_mu[r], -g_mu[r + DD], g_s[r], g_s[r + DD]);
            }
        }
        __syncthreads();

        #pragma unroll 1
        for (int g = 0; g < DK / 8; g++) {       // flush lg2 every 8 d's
            #pragma unroll
            for (int dp = 0; dp < 4; dp++) {     // d-pair (da, db)
                const int d = g * 8 + dp * 2;
                // i side: LDS.64 pairs, then dup-pack per k
                const float2* ipA = (const float2*)&s_i[ty][d];
                const float2* ipB = (const float2*)&s_i[ty][d + 1];
                float2 miA = ipA[0], siA = ipA[1];
                float2 miB = ipB[0], siB = ipB[1];
                u64 miA2[2] = { pk(miA.x, miA.x), pk(miA.y, miA.y) };
                u64 siA2[2] = { pk(siA.x, siA.x), pk(siA.y, siA.y) };
                u64 miB2[2] = { pk(miB.x, miB.x), pk(miB.y, miB.y) };
                u64 siB2[2] = { pk(siB.x, siB.x), pk(siB.y, siB.y) };
                // j side: packed pairs straight from shared (LDS.64)
                u64 mjA[2], sjA[2], mjB[2], sjB[2];
                #pragma unroll
                for (int jp = 0; jp < 2; jp++) {
                    const u64* jpA = (const u64*)&s_j[txj + 16 * jp][d];
                    const u64* jpB = (const u64*)&s_j[txj + 16 * jp][d + 1];
                    mjA[jp] = jpA[0]; sjA[jp] = jpA[1];
                    mjB[jp] = jpB[0]; sjB[jp] = jpB[1];
                }
                #pragma unroll
                for (int k = 0; k < 2; k++)
                    #pragma unroll
                    for (int jp = 0; jp < 2; jp++) {
                        u64 a  = fma2(siA2[k], ONE2, sjA[jp]);   // ssum @ da
                        u64 bb = fma2(siB2[k], ONE2, sjB[jp]);   // ssum @ db
                        u64 dA = fma2(miA2[k], ONE2, mjA[jp]);   // mu_i - mu_j
                        u64 dB = fma2(miB2[k], ONE2, mjB[jp]);
                        u64 sA = fma2(dA, dA, ZERO2);
                        u64 sB = fma2(dB, dB, ZERO2);
                        u64 den = fma2(a, bb, ZERO2);
                        u64 num = fma2(sA, bb, ZERO2);
                        num = fma2(sB, a, num);
                        float dl, dh; upk(den, dl, dh);
                        u64 rc = pk(frcp(dl), frcp(dh));
                        acc2[k][jp]  = fma2(num, rc, acc2[k][jp]);
                        prod2[k][jp] = fma2(prod2[k][jp], den, ZERO2);
                    }
            }
            // flush: acc += ln(prod of 8 ssums)
            #pragma unroll
            for (int k = 0; k < 2; k++)
                #pragma unroll
                for (int jp = 0; jp < 2; jp++) {
                    float pl, ph; upk(prod2[k][jp], pl, ph);
                    acc2[k][jp] = fma2(pk(flg2(pl), flg2(ph)), LN2_2, acc2[k][jp]);
                    prod2[k][jp] = ONE2;
                }
        }
    }

    // RED partial (-acc) into zero-initialized out; mirror unless diagonal tile.
    const bool diag = (ti == tj);
    #pragma unroll
    for (int k = 0; k < 2; k++) {
        int i = i0 + 2 * ty + k;
        #pragma unroll
        for (int jp = 0; jp < 2; jp++) {
            float v0, v1; upk(acc2[k][jp], v0, v1);
            int j = j0 + 2 * txj + 32 * jp;
            gred(&out[i * NN + j],     -v0);
            gred(&out[i * NN + j + 1], -v1);
            if (!diag) {
                gred(&out[j * NN + i],       -v0);
                gred(&out[(j + 1) * NN + i], -v1);
            }
        }
    }
}

extern "C" void kernel_launch(void* const* d_in, const int* in_sizes, int n_in,
                              void* d_out, int out_size) {
    const float* muX  = (const float*)d_in[0];
    const float* lsig = (const float*)d_in[1];
    float* out = (float*)d_out;

    prep_kernel<<<NN / 8, 256>>>(muX, lsig);
    zero_kernel<<<NN * NN / 4 / 256, 256>>>(out);

    dim3 grid(136, 2);   // dense triangular tiles x d-halves
    pair_kernel<<<grid, 512>>>(out);
}